// round 6
// baseline (speedup 1.0000x reference)
#include <cuda_runtime.h>
#include <math_constants.h>
#include <cstdint>

// Problem constants
#define BB 4
#define SS 4096
#define EE 256
#define DD 32

typedef unsigned long long ull;

// ---- packed f32x2 helpers (sm_103 FFMA2 path) ----
__device__ __forceinline__ ull ffma2(ull a, ull b, ull c) {
    ull d; asm("fma.rn.f32x2 %0, %1, %2, %3;" : "=l"(d) : "l"(a), "l"(b), "l"(c)); return d;
}
__device__ __forceinline__ ull fmul2(ull a, ull b) {
    ull d; asm("mul.rn.f32x2 %0, %1, %2;" : "=l"(d) : "l"(a), "l"(b)); return d;
}
__device__ __forceinline__ ull pack2(float x, float y) {
    ull r; asm("mov.b64 %0, {%1, %2};" : "=l"(r) : "f"(x), "f"(y)); return r;
}
__device__ __forceinline__ float2 unpack2(ull u) {
    float2 v; asm("mov.b64 {%0, %1}, %2;" : "=f"(v.x), "=f"(v.y) : "l"(u)); return v;
}

// ---- cp.async helpers ----
__device__ __forceinline__ uint32_t smem_u32(const void* p) {
    uint32_t a;
    asm("{ .reg .u64 t; cvta.to.shared.u64 t, %1; cvt.u32.u64 %0, t; }" : "=r"(a) : "l"(p));
    return a;
}
__device__ __forceinline__ void cp_async16(uint32_t dst, const void* src) {
    asm volatile("cp.async.cg.shared.global [%0], [%1], 16;" :: "r"(dst), "l"(src) : "memory");
}
#define CP_COMMIT() asm volatile("cp.async.commit_group;" ::: "memory")
#define CP_WAIT0()  asm volatile("cp.async.wait_group 0;" ::: "memory")

// Scratch for projected Q/K/V: [B, S, D] fp32 each (static)
__device__ float g_q[BB * SS * DD];
__device__ float g_k[BB * SS * DD];
__device__ float g_v[BB * SS * DD];

// ---------------------------------------------------------------------------
// Projection kernel, f32x2-packed over e-pairs. One block = 32 rows of x.
// ---------------------------------------------------------------------------
__global__ __launch_bounds__(256, 1) void proj_kernel(
    const float* __restrict__ x,
    const float* __restrict__ Wq,
    const float* __restrict__ Wk,
    const float* __restrict__ Wv)
{
    __shared__ float xs[32 * EE];  // 32 KB
    const int row0 = blockIdx.x * 32;
    const int tid = threadIdx.x;

    const float4* xg = (const float4*)(x + (size_t)row0 * EE);
    float4* xs4 = (float4*)xs;
#pragma unroll
    for (int i = 0; i < 8; i++) xs4[tid + i * 256] = xg[tid + i * 256];
    __syncthreads();

    const int col = tid & 31;
    const int rg  = tid >> 5;

    ull aq2[4], ak2[4], av2[4];
#pragma unroll
    for (int rr = 0; rr < 4; rr++) { aq2[rr] = 0; ak2[rr] = 0; av2[rr] = 0; }

#pragma unroll 2
    for (int e = 0; e < EE; e += 2) {
        const ull wq2 = pack2(__ldg(&Wq[e * DD + col]), __ldg(&Wq[(e + 1) * DD + col]));
        const ull wk2 = pack2(__ldg(&Wk[e * DD + col]), __ldg(&Wk[(e + 1) * DD + col]));
        const ull wv2 = pack2(__ldg(&Wv[e * DD + col]), __ldg(&Wv[(e + 1) * DD + col]));
#pragma unroll
        for (int rr = 0; rr < 4; rr++) {
            const ull xv2 = *(const ull*)&xs[(rg * 4 + rr) * EE + e];
            aq2[rr] = ffma2(xv2, wq2, aq2[rr]);
            ak2[rr] = ffma2(xv2, wk2, ak2[rr]);
            av2[rr] = ffma2(xv2, wv2, av2[rr]);
        }
    }

#pragma unroll
    for (int rr = 0; rr < 4; rr++) {
        const int r = row0 + rg * 4 + rr;
        const float2 q2 = unpack2(aq2[rr]);
        const float2 k2 = unpack2(ak2[rr]);
        const float2 v2 = unpack2(av2[rr]);
        g_q[r * DD + col] = q2.x + q2.y;
        g_k[r * DD + col] = k2.x + k2.y;
        g_v[r * DD + col] = v2.x + v2.y;
    }
}

// ---------------------------------------------------------------------------
// Flash attention: 512 threads, 2q x 4k per-thread tile, P in registers,
// FFMA2 math, cp.async double-buffered K/V. 16 warps/SM for latency hiding.
// Thread (qg 0..31, kg 0..15): queries qg+32i (i<2), keys kg+16j (j<4).
// Partial PV acc reduced over 16 kg lanes by width-16 butterflies at the end.
// ---------------------------------------------------------------------------
#define BQ 64
#define BK 64
#define KST 36   // smem row stride (floats): float4-aligned, conflict-free

__global__ __launch_bounds__(512, 1) void attn_kernel(float* __restrict__ out)
{
    __shared__ float qs[BQ * KST];        // 9.0 KB
    __shared__ float ks[2][BK * KST];     // 18.0 KB (double-buffered)
    __shared__ float vs[2][BK * KST];     // 18.0 KB

    const int b   = blockIdx.y;
    const int q0  = blockIdx.x * BQ;
    const int tid = threadIdx.x;
    const int qg  = tid >> 4;   // 0..31
    const int kg  = tid & 15;   // 0..15

    const float* qb = g_q + ((size_t)b * SS + q0) * DD;
    const float* kb = g_k + (size_t)b * SS * DD;
    const float* vb = g_v + (size_t)b * SS * DD;

    // Cooperative-load coordinates: 64 rows x 8 float4 = 512, one per thread.
    const int lrow = tid >> 3, lc = tid & 7;
    const int goff = lrow * DD + lc * 4;       // gmem float offset
    const int soff = lrow * KST + lc * 4;      // smem float offset

    // Load Q tile (plain LDG->STS; covered by first barrier).
    *(float4*)&qs[soff] = *(const float4*)(qb + goff);

    // Prologue: async-load chunk 0.
    cp_async16(smem_u32(&ks[0][soff]), kb + goff);
    cp_async16(smem_u32(&vs[0][soff]), vb + goff);
    CP_COMMIT();

    ull acc2[2][16];   // 2 queries x 32 dims as 16 f32x2 pairs (64 regs)
#pragma unroll
    for (int i = 0; i < 2; i++)
#pragma unroll
        for (int c = 0; c < 16; c++) acc2[i][c] = 0;

    float m[2], l[2];
#pragma unroll
    for (int i = 0; i < 2; i++) { m[i] = -CUDART_INF_F; l[i] = 0.f; }

    for (int nc = 0; nc < SS / BK; nc++) {
        const int db = nc & 1;
        CP_WAIT0();
        __syncthreads();   // chunk nc data ready; all warps done with buf db^1

        // Issue async loads for next chunk into the other buffer.
        if (nc + 1 < SS / BK) {
            const int kc2 = (nc + 1) * BK;
            cp_async16(smem_u32(&ks[db ^ 1][soff]), kb + (size_t)kc2 * DD + goff);
            cp_async16(smem_u32(&vs[db ^ 1][soff]), vb + (size_t)kc2 * DD + goff);
            CP_COMMIT();
        }

        const float* ksb = ks[db];
        const float* vsb = vs[db];

        // ---- QK: 2x4 tile, packed partial dots ----
        ull sp[2][4];
#pragma unroll
        for (int i = 0; i < 2; i++)
#pragma unroll
            for (int j = 0; j < 4; j++) sp[i][j] = 0;

#pragma unroll
        for (int e4 = 0; e4 < 8; e4++) {
            ulonglong2 qv[2], kv[4];
#pragma unroll
            for (int i = 0; i < 2; i++)
                qv[i] = *(const ulonglong2*)&qs[(qg + 32 * i) * KST + e4 * 4];
#pragma unroll
            for (int j = 0; j < 4; j++)
                kv[j] = *(const ulonglong2*)&ksb[(kg + 16 * j) * KST + e4 * 4];
#pragma unroll
            for (int i = 0; i < 2; i++)
#pragma unroll
                for (int j = 0; j < 4; j++) {
                    sp[i][j] = ffma2(qv[i].x, kv[j].x, sp[i][j]);
                    sp[i][j] = ffma2(qv[i].y, kv[j].y, sp[i][j]);
                }
        }

        // ---- online softmax; sp becomes packed (p,p) ----
#pragma unroll
        for (int i = 0; i < 2; i++) {
            float s[4];
#pragma unroll
            for (int j = 0; j < 4; j++) {
                const float2 t = unpack2(sp[i][j]);
                s[j] = t.x + t.y;
            }
            float rmax = fmaxf(fmaxf(s[0], s[1]), fmaxf(s[2], s[3]));
#pragma unroll
            for (int off = 1; off < 16; off <<= 1)
                rmax = fmaxf(rmax, __shfl_xor_sync(0xffffffffu, rmax, off, 16));

            if (rmax > m[i]) {               // record max: rescale (rare)
                const float corr = __expf(m[i] - rmax);
                l[i] *= corr;
                const ull c2 = pack2(corr, corr);
#pragma unroll
                for (int c = 0; c < 16; c++) acc2[i][c] = fmul2(acc2[i][c], c2);
                m[i] = rmax;
            }

            float psum = 0.f;
#pragma unroll
            for (int j = 0; j < 4; j++) {
                const float p = __expf(s[j] - m[i]);
                sp[i][j] = pack2(p, p);
                psum += p;
            }
#pragma unroll
            for (int off = 1; off < 16; off <<= 1)
                psum += __shfl_xor_sync(0xffffffffu, psum, off, 16);
            l[i] += psum;
        }

        // ---- PV: packed partial accumulation over this thread's 4 keys ----
#pragma unroll
        for (int c = 0; c < 8; c++) {
            ulonglong2 vv[4];
#pragma unroll
            for (int j = 0; j < 4; j++)
                vv[j] = *(const ulonglong2*)&vsb[(kg + 16 * j) * KST + c * 4];
#pragma unroll
            for (int i = 0; i < 2; i++)
#pragma unroll
                for (int j = 0; j < 4; j++) {
                    acc2[i][2 * c]     = ffma2(sp[i][j], vv[j].x, acc2[i][2 * c]);
                    acc2[i][2 * c + 1] = ffma2(sp[i][j], vv[j].y, acc2[i][2 * c + 1]);
                }
        }
    }

    // ---- butterfly-reduce partials over the 16 kg lanes; write out ----
    const float scaling = 0.17677669529663687f;  // 32^-0.5 (post-softmax, per reference)
#pragma unroll
    for (int i = 0; i < 2; i++) {
        const float inv = scaling / l[i];
        float* orow = out + ((size_t)b * SS + q0 + qg + 32 * i) * DD;
#pragma unroll
        for (int c = 0; c < 8; c++) {
            float2 lo = unpack2(acc2[i][2 * c]);
            float2 hi = unpack2(acc2[i][2 * c + 1]);
#pragma unroll
            for (int off = 1; off < 16; off <<= 1) {
                lo.x += __shfl_xor_sync(0xffffffffu, lo.x, off, 16);
                lo.y += __shfl_xor_sync(0xffffffffu, lo.y, off, 16);
                hi.x += __shfl_xor_sync(0xffffffffu, hi.x, off, 16);
                hi.y += __shfl_xor_sync(0xffffffffu, hi.y, off, 16);
            }
            if (kg == c) {
                float4 o;
                o.x = lo.x * inv; o.y = lo.y * inv;
                o.z = hi.x * inv; o.w = hi.y * inv;
                *(float4*)(orow + c * 4) = o;
            }
        }
    }
}

// ---------------------------------------------------------------------------
extern "C" void kernel_launch(void* const* d_in, const int* in_sizes, int n_in,
                              void* d_out, int out_size)
{
    const float* x  = (const float*)d_in[0];
    const float* Wq = (const float*)d_in[1];
    const float* Wk = (const float*)d_in[2];
    const float* Wv = (const float*)d_in[3];
    float* out = (float*)d_out;

    proj_kernel<<<(BB * SS) / 32, 256>>>(x, Wq, Wk, Wv);

    dim3 grid(SS / BQ, BB);
    attn_kernel<<<grid, 512>>>(out);
}